// round 2
// baseline (speedup 1.0000x reference)
#include <cuda_runtime.h>
#include <math.h>

#define Bn 32
#define T_EN 512
#define T_DE 2048
#define C_Qc 80
#define C_Kc 512
#define C_Ac 128
#define TEMPC 0.0005f

#define NEG_INF_DEV __int_as_float(0xff800000)

// ------------------------- scratch (device globals) -------------------------
__device__ float g_Wt1[1536 * 1024];
__device__ float g_Wt2[1024 * 128];
__device__ float g_Wq1[240 * 160];
__device__ float g_Wq2[160 * 80];
__device__ float g_Wq3[80 * 128];
__device__ float g_h1[16384L * 1024];
__device__ float g_kk[16384L * 128];
__device__ float g_kc[32L * 128 * 512];
__device__ float g_k2[16384];
__device__ float g_hq1[65536L * 160];
__device__ float g_hq2[65536L * 80];
__device__ float g_qq[65536L * 128];
__device__ float g_q2[65536];
__device__ float g_logits[33554432L];
__device__ float g_plogT[33554432L];
__device__ unsigned g_dirs[32L * 2048 * 16];
__device__ int g_idx[32 * 2048];

// ------------------------- weight prep -------------------------
// conv weight [N][Cin][3] -> wt[(dt*Cin+ci)*N + n]
__global__ void wprep_conv(const float* __restrict__ w, float* __restrict__ wt, int N, int Cin) {
    int idx = blockIdx.x * 256 + threadIdx.x;
    int total = N * Cin * 3;
    if (idx < total) {
        int n = idx / (Cin * 3);
        int rem = idx - n * (Cin * 3);
        int ci = rem / 3;
        int dt = rem - ci * 3;
        wt[(dt * Cin + ci) * N + n] = w[idx];
    }
}
// 1x1 weight [N][K] -> wt[k*N + n]
__global__ void wprep_1x1(const float* __restrict__ w, float* __restrict__ wt, int N, int K) {
    int idx = blockIdx.x * 256 + threadIdx.x;
    if (idx < N * K) {
        int n = idx / K;
        int k = idx - n * K;
        wt[k * N + n] = w[idx];
    }
}

// ------------------------- generic GEMM -------------------------
// C[M][N] = epilogue( act(A)[M][K] @ W[K][N] )
// IM2COL: A gathered from X[b][t][Cin] with kernel-3 pad-1 conv patches, k = dt*Cin+ci
// EPI==0: C = acc + bias[n]
// EPI==1: C = -TEMP * (rown[m] + coln[n] - 2*acc)     (batched dist)
template <int IM2COL, bool RELUIN, int EPI>
__global__ __launch_bounds__(256) void gemm_k(
    const float* __restrict__ A, const float* __restrict__ W,
    const float* __restrict__ bias, float* __restrict__ C,
    int M, int N, int K, int ldA, int ldW, int ldC,
    int Cin, int Tlen,
    long sAb, long sWb, long sCb,
    const float* __restrict__ rown, const float* __restrict__ coln,
    int rstride, int cstride)
{
    __shared__ float As[16][128];
    __shared__ float Ws[16][128];
    const int bm = blockIdx.y * 128;
    const int bn = blockIdx.x * 128;
    const int bz = blockIdx.z;
    A += sAb * bz; W += sWb * bz; C += sCb * bz;
    const int tid = threadIdx.x;
    const int tx = tid & 15, ty = tid >> 4;

    float acc[8][8];
#pragma unroll
    for (int i = 0; i < 8; i++)
#pragma unroll
        for (int j = 0; j < 8; j++) acc[i][j] = 0.f;

    for (int kb = 0; kb < K; kb += 16) {
#pragma unroll
        for (int r = 0; r < 2; r++) {
            int f = tid + r * 256;
            int m = f >> 2;
            int kq = (f & 3) << 2;
            int gk = kb + kq;
            float4 v = make_float4(0.f, 0.f, 0.f, 0.f);
            if (IM2COL) {
                int gm = bm + m;
                int bb = gm / Tlen;
                int t = gm - bb * Tlen;
                int dt = gk / Cin;
                int ci = gk - dt * Cin;
                int tt = t + dt - 1;
                if (tt >= 0 && tt < Tlen)
                    v = *(const float4*)(A + ((long)(bb * Tlen + tt)) * Cin + ci);
            } else {
                v = *(const float4*)(A + (long)(bm + m) * ldA + gk);
            }
            if (RELUIN) {
                v.x = fmaxf(v.x, 0.f); v.y = fmaxf(v.y, 0.f);
                v.z = fmaxf(v.z, 0.f); v.w = fmaxf(v.w, 0.f);
            }
            As[kq + 0][m] = v.x; As[kq + 1][m] = v.y;
            As[kq + 2][m] = v.z; As[kq + 3][m] = v.w;
        }
#pragma unroll
        for (int r = 0; r < 2; r++) {
            int f = tid + r * 256;
            int kk2 = f >> 5;
            int n4 = (f & 31) << 2;
            int gn = bn + n4;
            float4 v = make_float4(0.f, 0.f, 0.f, 0.f);
            if (gn < N)
                v = *(const float4*)(W + (long)(kb + kk2) * ldW + gn);
            Ws[kk2][n4 + 0] = v.x; Ws[kk2][n4 + 1] = v.y;
            Ws[kk2][n4 + 2] = v.z; Ws[kk2][n4 + 3] = v.w;
        }
        __syncthreads();
#pragma unroll
        for (int k = 0; k < 16; k++) {
            float a[8], b[8];
#pragma unroll
            for (int i = 0; i < 8; i++) a[i] = As[k][ty * 8 + i];
#pragma unroll
            for (int j = 0; j < 8; j++) b[j] = Ws[k][tx * 8 + j];
#pragma unroll
            for (int i = 0; i < 8; i++)
#pragma unroll
                for (int j = 0; j < 8; j++) acc[i][j] = fmaf(a[i], b[j], acc[i][j]);
        }
        __syncthreads();
    }

#pragma unroll
    for (int i = 0; i < 8; i++) {
        int gm = bm + ty * 8 + i;
#pragma unroll
        for (int j = 0; j < 8; j++) {
            int gn = bn + tx * 8 + j;
            if (gn < N) {
                float v = acc[i][j];
                if (EPI == 0) {
                    if (bias) v += bias[gn];
                } else {
                    v = -TEMPC * (rown[(long)rstride * bz + gm] +
                                  coln[(long)cstride * bz + gn] - 2.f * v);
                }
                C[(long)gm * ldC + gn] = v;
            }
        }
    }
}

// ------------------------- row squared-norms -------------------------
// X [rows][128] -> out[row] = sum X^2
__global__ void rowsq(const float* __restrict__ X, float* __restrict__ out) {
    int row = blockIdx.x * 8 + threadIdx.y;
    const float4* p = (const float4*)(X + (long)row * 128);
    float4 a = p[threadIdx.x];
    float s = a.x * a.x + a.y * a.y + a.z * a.z + a.w * a.w;
#pragma unroll
    for (int o = 16; o; o >>= 1) s += __shfl_xor_sync(0xffffffffu, s, o);
    if (threadIdx.x == 0) out[row] = s;
}

// ------------------------- transposes -------------------------
// kk [(b*512+s)][128] -> kc [b][128][512]
__global__ void kctrans(const float* __restrict__ kk, float* __restrict__ kc) {
    __shared__ float tile[32][33];
    int b = blockIdx.z;
    int s0 = blockIdx.x * 32, c0 = blockIdx.y * 32;
    tile[threadIdx.y][threadIdx.x] =
        kk[((long)(b * 512 + s0 + threadIdx.y)) * 128 + c0 + threadIdx.x];
    __syncthreads();
    kc[((long)(b * 128 + c0 + threadIdx.y)) * 512 + s0 + threadIdx.x] =
        tile[threadIdx.x][threadIdx.y];
}

// prior [b][512][2048] -> plogT[b][2048][512] = log(prior + 1e-8)
__global__ void prior_t(const float* __restrict__ pr, float* __restrict__ plogT) {
    __shared__ float tile[32][33];
    int b = blockIdx.z;
    int s0 = blockIdx.x * 32, t0 = blockIdx.y * 32;
    tile[threadIdx.y][threadIdx.x] =
        pr[((long)b * 512 + s0 + threadIdx.y) * 2048 + t0 + threadIdx.x];
    __syncthreads();
    plogT[((long)b * 2048 + t0 + threadIdx.y) * 512 + s0 + threadIdx.x] =
        logf(tile[threadIdx.x][threadIdx.y] + 1e-8f);
}

// ------------------------- fused row softmax -------------------------
__device__ __forceinline__ float blockMax4(float v) {
    __shared__ float sm[4];
#pragma unroll
    for (int o = 16; o; o >>= 1) v = fmaxf(v, __shfl_xor_sync(0xffffffffu, v, o));
    if ((threadIdx.x & 31) == 0) sm[threadIdx.x >> 5] = v;
    __syncthreads();
    v = fmaxf(fmaxf(sm[0], sm[1]), fmaxf(sm[2], sm[3]));
    __syncthreads();
    return v;
}
__device__ __forceinline__ float blockSum4(float v) {
    __shared__ float sm[4];
#pragma unroll
    for (int o = 16; o; o >>= 1) v += __shfl_xor_sync(0xffffffffu, v, o);
    if ((threadIdx.x & 31) == 0) sm[threadIdx.x >> 5] = v;
    __syncthreads();
    v = sm[0] + sm[1] + sm[2] + sm[3];
    __syncthreads();
    return v;
}

// per (b,t) row over s=0..511: logp = logsoftmax(logits) + plogT; attn = softmax(logp)
__global__ __launch_bounds__(128) void softmax_row(
    const float* __restrict__ logits, const float* __restrict__ plogT,
    float* __restrict__ out_logp, float* __restrict__ out_attn)
{
    long row = blockIdx.x;
    const float* l = logits + row * 512;
    const float* pl = plogT + row * 512;
    int tid = threadIdx.x;
    float v[4], p[4];
#pragma unroll
    for (int r = 0; r < 4; r++) { v[r] = l[r * 128 + tid]; p[r] = pl[r * 128 + tid]; }
    float m = fmaxf(fmaxf(v[0], v[1]), fmaxf(v[2], v[3]));
    m = blockMax4(m);
    float s = 0.f;
#pragma unroll
    for (int r = 0; r < 4; r++) s += __expf(v[r] - m);
    s = blockSum4(s);
    float lse = m + logf(s);
    float lp[4];
#pragma unroll
    for (int r = 0; r < 4; r++) lp[r] = v[r] - lse + p[r];
    float m2 = fmaxf(fmaxf(lp[0], lp[1]), fmaxf(lp[2], lp[3]));
    m2 = blockMax4(m2);
    float s2 = 0.f;
#pragma unroll
    for (int r = 0; r < 4; r++) s2 += __expf(lp[r] - m2);
    s2 = blockSum4(s2);
    float inv = 1.f / s2;
#pragma unroll
    for (int r = 0; r < 4; r++) {
        out_logp[row * 512 + r * 128 + tid] = lp[r];
        out_attn[row * 512 + r * 128 + tid] = __expf(lp[r] - m2) * inv;
    }
}

// ------------------------- MAS forward DP -------------------------
// value[b][i][j] = attn[b][j][i]; v_new[i] = (i<=j) ? max(v[i], v[i-1]) + value : -inf
// dir bit = (v[i] >= v[i-1]) packed via ballot into dirs[b][j][warp]
__global__ __launch_bounds__(512) void mas_fwd(const float* __restrict__ attn,
                                               unsigned* __restrict__ dirs)
{
    const int b = blockIdx.x;
    const int i = threadIdx.x;
    __shared__ float vbuf[2][513];
    if (i == 0) { vbuf[0][0] = NEG_INF_DEV; vbuf[1][0] = NEG_INF_DEV; }
    float v = 0.f;
    vbuf[0][i + 1] = 0.f;
    __syncthreads();
    const float* arow = attn + (long)b * T_DE * T_EN + i;
    const unsigned lane = i & 31, wid = i >> 5;
    unsigned* drow = dirs + (long)b * T_DE * 16 + wid;
    float pf[8];
#pragma unroll
    for (int r = 0; r < 8; r++) pf[r] = arow[r * 512];
    int p = 0;
    for (int jj = 0; jj < 2048; jj += 8) {
#pragma unroll
        for (int r = 0; r < 8; r++) {
            int j = jj + r;
            float vj = pf[r];
            if (jj + 8 + r < 2048) pf[r] = arow[(jj + 8 + r) * 512];
            float vl = vbuf[p][i];
            bool dir = (v >= vl);
            unsigned bal = __ballot_sync(0xffffffffu, dir);
            if (lane == 0) drow[(long)j * 16] = bal;
            float vmax = dir ? v : vl;
            v = (i <= j) ? (vmax + vj) : NEG_INF_DEV;
            vbuf[p ^ 1][i + 1] = v;
            __syncthreads();
            p ^= 1;
        }
    }
}

// ------------------------- MAS backtrack -------------------------
__global__ __launch_bounds__(512) void mas_bwd(const unsigned* __restrict__ dirs,
                                               int* __restrict__ idxg,
                                               float* __restrict__ durf)
{
    extern __shared__ unsigned sd[];          // 2048*16 u32 = 128 KB
    __shared__ unsigned short sidx[2048];
    __shared__ int cnt[512];
    int b = blockIdx.x, tid = threadIdx.x;
    for (int f = tid; f < 2048 * 16; f += 512) sd[f] = dirs[(long)b * 2048 * 16 + f];
    if (tid < 512) cnt[tid] = 0;
    __syncthreads();
    if (tid == 0) {
        int idx = T_EN - 1;
        for (int j = 2047; j >= 0; j--) {
            sidx[j] = (unsigned short)idx;
            cnt[idx]++;
            unsigned w = sd[j * 16 + (idx >> 5)];
            int d = (w >> (idx & 31)) & 1;
            idx += d - 1;
        }
    }
    __syncthreads();
    for (int f = tid; f < 2048; f += 512) idxg[b * 2048 + f] = (int)sidx[f];
    if (tid < 512) durf[b * 512 + tid] = (float)cnt[tid];
}

// ------------------------- one-hot fill of mas output -------------------------
__global__ __launch_bounds__(128) void mas_fill(const int* __restrict__ idxg,
                                                float* __restrict__ masout)
{
    long row = blockIdx.x;
    int id = idxg[row];
    int tid = threadIdx.x;
    float4 v = make_float4(0.f, 0.f, 0.f, 0.f);
    if ((id >> 2) == tid) ((float*)&v)[id & 3] = 1.f;
    ((float4*)(masout + row * 512))[tid] = v;
}

// ------------------------- launcher -------------------------
extern "C" void kernel_launch(void* const* d_in, const int* in_sizes, int n_in,
                              void* d_out, int out_size) {
    const float* x   = (const float*)d_in[0];   // [32,512,512]
    const float* y   = (const float*)d_in[1];   // [32,2048,80]
    const float* pr  = (const float*)d_in[4];   // [32,512,2048]
    const float* kw1 = (const float*)d_in[5];
    const float* kb1 = (const float*)d_in[6];
    const float* kw2 = (const float*)d_in[7];
    const float* kb2 = (const float*)d_in[8];
    const float* qw1 = (const float*)d_in[9];
    const float* qb1 = (const float*)d_in[10];
    const float* qw2 = (const float*)d_in[11];
    const float* qb2 = (const float*)d_in[12];
    const float* qw3 = (const float*)d_in[13];
    const float* qb3 = (const float*)d_in[14];

    float* out = (float*)d_out;
    float* out_logp = out;
    float* out_attn = out + 33554432L;
    float* out_mas  = out + 67108864L;
    float* out_dur  = out + 100663296L;

    float *Wt1, *Wt2, *Wq1, *Wq2, *Wq3, *h1, *kk, *kc, *k2, *hq1, *hq2, *qq, *q2, *logits, *plogT;
    unsigned* dirs; int* idxg;
    cudaGetSymbolAddress((void**)&Wt1, g_Wt1);
    cudaGetSymbolAddress((void**)&Wt2, g_Wt2);
    cudaGetSymbolAddress((void**)&Wq1, g_Wq1);
    cudaGetSymbolAddress((void**)&Wq2, g_Wq2);
    cudaGetSymbolAddress((void**)&Wq3, g_Wq3);
    cudaGetSymbolAddress((void**)&h1, g_h1);
    cudaGetSymbolAddress((void**)&kk, g_kk);
    cudaGetSymbolAddress((void**)&kc, g_kc);
    cudaGetSymbolAddress((void**)&k2, g_k2);
    cudaGetSymbolAddress((void**)&hq1, g_hq1);
    cudaGetSymbolAddress((void**)&hq2, g_hq2);
    cudaGetSymbolAddress((void**)&qq, g_qq);
    cudaGetSymbolAddress((void**)&q2, g_q2);
    cudaGetSymbolAddress((void**)&logits, g_logits);
    cudaGetSymbolAddress((void**)&plogT, g_plogT);
    cudaGetSymbolAddress((void**)&dirs, g_dirs);
    cudaGetSymbolAddress((void**)&idxg, g_idx);

    // weight prep
    wprep_conv<<<(1024 * 512 * 3 + 255) / 256, 256>>>(kw1, Wt1, 1024, 512);
    wprep_conv<<<(160 * 80 * 3 + 255) / 256, 256>>>(qw1, Wq1, 160, 80);
    wprep_1x1<<<(128 * 1024 + 255) / 256, 256>>>(kw2, Wt2, 128, 1024);
    wprep_1x1<<<(80 * 160 + 255) / 256, 256>>>(qw2, Wq2, 80, 160);
    wprep_1x1<<<(128 * 80 + 255) / 256, 256>>>(qw3, Wq3, 128, 80);

    // k path: conv3(im2col GEMM) -> relu -> 1x1 GEMM
    gemm_k<1, false, 0><<<dim3(8, 128, 1), 256>>>(
        x, Wt1, kb1, h1, 16384, 1024, 1536, 0, 1024, 1024, 512, 512,
        0, 0, 0, nullptr, nullptr, 0, 0);
    gemm_k<0, true, 0><<<dim3(1, 128, 1), 256>>>(
        h1, Wt2, kb2, kk, 16384, 128, 1024, 1024, 128, 128, 0, 0,
        0, 0, 0, nullptr, nullptr, 0, 0);
    rowsq<<<16384 / 8, dim3(32, 8)>>>(kk, k2);
    kctrans<<<dim3(16, 4, 32), dim3(32, 32)>>>(kk, kc);

    // q path: conv3 -> relu -> 1x1 -> relu -> 1x1
    gemm_k<1, false, 0><<<dim3(2, 512, 1), 256>>>(
        y, Wq1, qb1, hq1, 65536, 160, 240, 0, 160, 160, 80, 2048,
        0, 0, 0, nullptr, nullptr, 0, 0);
    gemm_k<0, true, 0><<<dim3(1, 512, 1), 256>>>(
        hq1, Wq2, qb2, hq2, 65536, 80, 160, 160, 80, 80, 0, 0,
        0, 0, 0, nullptr, nullptr, 0, 0);
    gemm_k<0, true, 0><<<dim3(1, 512, 1), 256>>>(
        hq2, Wq3, qb3, qq, 65536, 128, 80, 80, 128, 128, 0, 0,
        0, 0, 0, nullptr, nullptr, 0, 0);
    rowsq<<<65536 / 8, dim3(32, 8)>>>(qq, q2);

    // prior transpose + log
    prior_t<<<dim3(16, 64, 32), dim3(32, 32)>>>(pr, plogT);

    // dist GEMM (batched): logits[b][t][s] = -TEMP * (q2+k2-2qk)
    gemm_k<0, false, 1><<<dim3(4, 16, 32), 256>>>(
        qq, kc, nullptr, logits, 2048, 512, 128, 128, 512, 512, 0, 0,
        2048L * 128, 128L * 512, 2048L * 512, q2, k2, 2048, 512);

    // fused log_softmax + prior + softmax per row
    softmax_row<<<65536, 128>>>(logits, plogT, out_logp, out_attn);

    // MAS forward DP + backtrack + fill
    mas_fwd<<<32, 512>>>(out_attn, dirs);
    cudaFuncSetAttribute(mas_bwd, cudaFuncAttributeMaxDynamicSharedMemorySize, 131072);
    mas_bwd<<<32, 512, 131072>>>(dirs, idxg, out_dur);
    mas_fill<<<65536, 128>>>(idxg, out_mas);
}

// round 4
// speedup vs baseline: 1.8716x; 1.8716x over previous
#include <cuda_runtime.h>
#include <math.h>
#include <stdint.h>

#define T_EN 512
#define T_DE 2048
#define TEMPC 0.0005f
#define NEG_INF_DEV __int_as_float(0xff800000)

__device__ __forceinline__ uint32_t f2tf(float x) {
    uint32_t r;
    asm("cvt.rna.tf32.f32 %0, %1;" : "=r"(r) : "f"(x));
    return r;
}

// ------------------------- scratch (device globals) -------------------------
__device__ float g_Wt1[1024L * 1536];
__device__ float g_Wq1[160 * 240];
__device__ float g_h1[16384L * 1024];
__device__ float g_kk[16384L * 128];
__device__ float g_k2[16384];
__device__ float g_hq1[65536L * 160];
__device__ float g_hq2[65536L * 80];
__device__ float g_qq[65536L * 128];
__device__ float g_q2[65536];
__device__ float g_logits[33554432L];
__device__ float g_plogT[33554432L];
__device__ unsigned g_dirs[32L * 2048 * 16];
__device__ int g_idx[32 * 2048];

// ------------------------- weight prep: [N][Cin][3] -> [N][dt*Cin+ci] -------------------------
__global__ void wprep_convT(const float* __restrict__ w, float* __restrict__ wt, int N, int Cin) {
    int idx = blockIdx.x * 256 + threadIdx.x;
    int total = N * Cin * 3;
    if (idx < total) {
        int n = idx / (Cin * 3);
        int rem = idx - n * (Cin * 3);
        int ci = rem / 3;
        int dt = rem - ci * 3;
        wt[(long)n * (3 * Cin) + dt * Cin + ci] = w[idx];
    }
}

// ------------------------- tf32 mma.sync GEMM -------------------------
// C[M][N] = epi( act(A)[M][K] @ B^T ), B stored [N][K] row-major.
// Block tile 128x128, BK=16, 8 warps (4m x 2n), warp tile 32x64.
// IM2COL: A gathered from X[b][t][Cin], conv kernel-3 pad-1, k = dt*Cin+ci.
// EPI0: + bias[n].  EPI1: -TEMP*(rown[m]+coln[n]-2*acc)
template <int IM2COL, bool RELUIN, int EPI>
__global__ __launch_bounds__(256, 2) void tgemm(
    const float* __restrict__ A, const float* __restrict__ B,
    const float* __restrict__ bias, float* __restrict__ C,
    int N, int K, int ldA, int ldB, int ldC,
    int Cin, int Tlen,
    long sAb, long sBb, long sCb,
    const float* __restrict__ rown, const float* __restrict__ coln,
    int rstride, int cstride)
{
    __shared__ uint32_t As[2][16][136];
    __shared__ uint32_t Bs[2][16][136];
    const int tid = threadIdx.x;
    const int lane = tid & 31, wid = tid >> 5;
    const int bn = blockIdx.x * 128;
    const int bm = blockIdx.y * 128;
    const int bz = blockIdx.z;
    A += sAb * bz; B += sBb * bz; C += sCb * bz;
    const int wm = wid & 3, wn = wid >> 2;

    float acc[2][8][4];
#pragma unroll
    for (int i = 0; i < 2; i++)
#pragma unroll
        for (int j = 0; j < 8; j++)
#pragma unroll
            for (int q = 0; q < 4; q++) acc[i][j][q] = 0.f;

    const int lrow = tid >> 2;            // 0..63 (per 256-chunk: row = fid>>2)
    const int lkq = (tid & 3) << 2;

    float4 ar0, ar1, br0, br1;

    // ---- tile loaders ----
    auto loadA = [&](int kb, int r) -> float4 {
        int row = lrow + r * 64;
        int gk = kb + lkq;
        float4 v = make_float4(0.f, 0.f, 0.f, 0.f);
        if (IM2COL) {
            int gm = bm + row;
            int bb = gm / Tlen;
            int t = gm - bb * Tlen;
            int dt = gk / Cin;
            int ci = gk - dt * Cin;
            int tt = t + dt - 1;
            if (tt >= 0 && tt < Tlen)
                v = *(const float4*)(A + ((long)(bb * Tlen + tt)) * Cin + ci);
        } else {
            v = *(const float4*)(A + (long)(bm + row) * ldA + gk);
            if (RELUIN) {
                v.x = fmaxf(v.x, 0.f); v.y = fmaxf(v.y, 0.f);
                v.z = fmaxf(v.z, 0.f); v.w = fmaxf(v.w, 0.f);
            }
        }
        return v;
    };
    auto loadB = [&](int kb, int r) -> float4 {
        int row = lrow + r * 64;
        float4 v = make_float4(0.f, 0.f, 0.f, 0.f);
        if (bn + row < N)
            v = *(const float4*)(B + (long)(bn + row) * ldB + kb + lkq);
        return v;
    };
    auto stsA = [&](int p, int r, float4 v) {
        int row = lrow + r * 64;
        As[p][lkq + 0][row] = f2tf(v.x);
        As[p][lkq + 1][row] = f2tf(v.y);
        As[p][lkq + 2][row] = f2tf(v.z);
        As[p][lkq + 3][row] = f2tf(v.w);
    };
    auto stsB = [&](int p, int r, float4 v) {
        int row = lrow + r * 64;
        Bs[p][lkq + 0][row] = f2tf(v.x);
        Bs[p][lkq + 1][row] = f2tf(v.y);
        Bs[p][lkq + 2][row] = f2tf(v.z);
        Bs[p][lkq + 3][row] = f2tf(v.w);
    };

    // ---- prologue ----
    ar0 = loadA(0, 0); ar1 = loadA(0, 1);
    br0 = loadB(0, 0); br1 = loadB(0, 1);
    stsA(0, 0, ar0); stsA(0, 1, ar1);
    stsB(0, 0, br0); stsB(0, 1, br1);
    __syncthreads();

    const int nc = K >> 4;
    for (int c = 0; c < nc; c++) {
        const int p = c & 1;
        if (c + 1 < nc) {
            int kb = (c + 1) << 4;
            ar0 = loadA(kb, 0); ar1 = loadA(kb, 1);
            br0 = loadB(kb, 0); br1 = loadB(kb, 1);
        }
#pragma unroll
        for (int ks = 0; ks < 2; ks++) {
            const int k0 = ks * 8 + (lane & 3);
            uint32_t af[2][4];
#pragma unroll
            for (int mi = 0; mi < 2; mi++) {
                int row = wm * 32 + mi * 16 + (lane >> 2);
                af[mi][0] = As[p][k0][row];
                af[mi][1] = As[p][k0][row + 8];
                af[mi][2] = As[p][k0 + 4][row];
                af[mi][3] = As[p][k0 + 4][row + 8];
            }
#pragma unroll
            for (int ni = 0; ni < 8; ni++) {
                int col = wn * 64 + ni * 8 + (lane >> 2);
                uint32_t bf0 = Bs[p][k0][col];
                uint32_t bf1 = Bs[p][k0 + 4][col];
#pragma unroll
                for (int mi = 0; mi < 2; mi++) {
                    asm volatile(
                        "mma.sync.aligned.m16n8k8.row.col.f32.tf32.tf32.f32 "
                        "{%0,%1,%2,%3}, {%4,%5,%6,%7}, {%8,%9}, {%0,%1,%2,%3};"
                        : "+f"(acc[mi][ni][0]), "+f"(acc[mi][ni][1]),
                          "+f"(acc[mi][ni][2]), "+f"(acc[mi][ni][3])
                        : "r"(af[mi][0]), "r"(af[mi][1]), "r"(af[mi][2]), "r"(af[mi][3]),
                          "r"(bf0), "r"(bf1));
                }
            }
        }
        if (c + 1 < nc) {
            int pn = p ^ 1;
            stsA(pn, 0, ar0); stsA(pn, 1, ar1);
            stsB(pn, 0, br0); stsB(pn, 1, br1);
        }
        __syncthreads();
    }

    // ---- epilogue ----
#pragma unroll
    for (int mi = 0; mi < 2; mi++) {
        int r0 = bm + wm * 32 + mi * 16 + (lane >> 2);
        float ra0 = 0.f, ra1 = 0.f;
        if (EPI == 1) {
            ra0 = rown[(long)rstride * bz + r0];
            ra1 = rown[(long)rstride * bz + r0 + 8];
        }
#pragma unroll
        for (int ni = 0; ni < 8; ni++) {
            int colb = bn + wn * 64 + ni * 8;
            if (colb < N) {
                int col = colb + (lane & 3) * 2;
                float2 v0, v1;
                if (EPI == 0) {
                    float bb0 = bias[col], bb1 = bias[col + 1];
                    v0.x = acc[mi][ni][0] + bb0; v0.y = acc[mi][ni][1] + bb1;
                    v1.x = acc[mi][ni][2] + bb0; v1.y = acc[mi][ni][3] + bb1;
                } else {
                    float cn0 = coln[(long)cstride * bz + col];
                    float cn1 = coln[(long)cstride * bz + col + 1];
                    v0.x = -TEMPC * (ra0 + cn0 - 2.f * acc[mi][ni][0]);
                    v0.y = -TEMPC * (ra0 + cn1 - 2.f * acc[mi][ni][1]);
                    v1.x = -TEMPC * (ra1 + cn0 - 2.f * acc[mi][ni][2]);
                    v1.y = -TEMPC * (ra1 + cn1 - 2.f * acc[mi][ni][3]);
                }
                *(float2*)(C + (long)r0 * ldC + col) = v0;
                *(float2*)(C + (long)(r0 + 8) * ldC + col) = v1;
            }
        }
    }
}

// ------------------------- row squared-norms -------------------------
__global__ void rowsq(const float* __restrict__ X, float* __restrict__ out) {
    int row = blockIdx.x * 8 + threadIdx.y;
    const float4* p = (const float4*)(X + (long)row * 128);
    float4 a = p[threadIdx.x];
    float s = a.x * a.x + a.y * a.y + a.z * a.z + a.w * a.w;
#pragma unroll
    for (int o = 16; o; o >>= 1) s += __shfl_xor_sync(0xffffffffu, s, o);
    if (threadIdx.x == 0) out[row] = s;
}

// prior [b][512][2048] -> plogT[b][2048][512] = log(prior + 1e-8)
__global__ void prior_t(const float* __restrict__ pr, float* __restrict__ plogT) {
    __shared__ float tile[32][33];
    int b = blockIdx.z;
    int s0 = blockIdx.x * 32, t0 = blockIdx.y * 32;
    tile[threadIdx.y][threadIdx.x] =
        pr[((long)b * 512 + s0 + threadIdx.y) * 2048 + t0 + threadIdx.x];
    __syncthreads();
    plogT[((long)b * 2048 + t0 + threadIdx.y) * 512 + s0 + threadIdx.x] =
        logf(tile[threadIdx.x][threadIdx.y] + 1e-8f);
}

// ------------------------- fused row softmax -------------------------
__device__ __forceinline__ float blockMax4(float v) {
    __shared__ float sm[4];
#pragma unroll
    for (int o = 16; o; o >>= 1) v = fmaxf(v, __shfl_xor_sync(0xffffffffu, v, o));
    if ((threadIdx.x & 31) == 0) sm[threadIdx.x >> 5] = v;
    __syncthreads();
    v = fmaxf(fmaxf(sm[0], sm[1]), fmaxf(sm[2], sm[3]));
    __syncthreads();
    return v;
}
__device__ __forceinline__ float blockSum4(float v) {
    __shared__ float sm[4];
#pragma unroll
    for (int o = 16; o; o >>= 1) v += __shfl_xor_sync(0xffffffffu, v, o);
    if ((threadIdx.x & 31) == 0) sm[threadIdx.x >> 5] = v;
    __syncthreads();
    v = sm[0] + sm[1] + sm[2] + sm[3];
    __syncthreads();
    return v;
}

__global__ __launch_bounds__(128) void softmax_row(
    const float* __restrict__ logits, const float* __restrict__ plogT,
    float* __restrict__ out_logp, float* __restrict__ out_attn)
{
    long row = blockIdx.x;
    const float* l = logits + row * 512;
    const float* pl = plogT + row * 512;
    int tid = threadIdx.x;
    float v[4], p[4];
#pragma unroll
    for (int r = 0; r < 4; r++) { v[r] = l[r * 128 + tid]; p[r] = pl[r * 128 + tid]; }
    float m = fmaxf(fmaxf(v[0], v[1]), fmaxf(v[2], v[3]));
    m = blockMax4(m);
    float s = 0.f;
#pragma unroll
    for (int r = 0; r < 4; r++) s += __expf(v[r] - m);
    s = blockSum4(s);
    float lse = m + logf(s);
    float lp[4];
#pragma unroll
    for (int r = 0; r < 4; r++) lp[r] = v[r] - lse + p[r];
    float m2 = fmaxf(fmaxf(lp[0], lp[1]), fmaxf(lp[2], lp[3]));
    m2 = blockMax4(m2);
    float s2 = 0.f;
#pragma unroll
    for (int r = 0; r < 4; r++) s2 += __expf(lp[r] - m2);
    s2 = blockSum4(s2);
    float inv = 1.f / s2;
#pragma unroll
    for (int r = 0; r < 4; r++) {
        out_logp[row * 512 + r * 128 + tid] = lp[r];
        out_attn[row * 512 + r * 128 + tid] = __expf(lp[r] - m2) * inv;
    }
}

// ------------------------- MAS forward DP -------------------------
__global__ __launch_bounds__(512) void mas_fwd(const float* __restrict__ attn,
                                               unsigned* __restrict__ dirs)
{
    const int b = blockIdx.x;
    const int i = threadIdx.x;
    __shared__ float vbuf[2][513];
    if (i == 0) { vbuf[0][0] = NEG_INF_DEV; vbuf[1][0] = NEG_INF_DEV; }
    float v = 0.f;
    vbuf[0][i + 1] = 0.f;
    __syncthreads();
    const float* arow = attn + (long)b * T_DE * T_EN + i;
    const unsigned lane = i & 31, wid = i >> 5;
    unsigned* drow = dirs + (long)b * T_DE * 16 + wid;
    float pf[8];
#pragma unroll
    for (int r = 0; r < 8; r++) pf[r] = arow[r * 512];
    int p = 0;
    for (int jj = 0; jj < 2048; jj += 8) {
#pragma unroll
        for (int r = 0; r < 8; r++) {
            int j = jj + r;
            float vj = pf[r];
            if (jj + 8 + r < 2048) pf[r] = arow[(jj + 8 + r) * 512];
            float vl = vbuf[p][i];
            bool dir = (v >= vl);
            unsigned bal = __ballot_sync(0xffffffffu, dir);
            if (lane == 0) drow[(long)j * 16] = bal;
            float vmax = dir ? v : vl;
            v = (i <= j) ? (vmax + vj) : NEG_INF_DEV;
            vbuf[p ^ 1][i + 1] = v;
            __syncthreads();
            p ^= 1;
        }
    }
}

// ------------------------- MAS backtrack -------------------------
__global__ __launch_bounds__(512) void mas_bwd(const unsigned* __restrict__ dirs,
                                               int* __restrict__ idxg,
                                               float* __restrict__ durf)
{
    extern __shared__ unsigned sd[];
    __shared__ unsigned short sidx[2048];
    __shared__ int cnt[512];
    int b = blockIdx.x, tid = threadIdx.x;
    for (int f = tid; f < 2048 * 16; f += 512) sd[f] = dirs[(long)b * 2048 * 16 + f];
    if (tid < 512) cnt[tid] = 0;
    __syncthreads();
    if (tid == 0) {
        int idx = T_EN - 1;
        for (int j = 2047; j >= 0; j--) {
            sidx[j] = (unsigned short)idx;
            cnt[idx]++;
            unsigned w = sd[j * 16 + (idx >> 5)];
            int d = (w >> (idx & 31)) & 1;
            idx += d - 1;
        }
    }
    __syncthreads();
    for (int f = tid; f < 2048; f += 512) idxg[b * 2048 + f] = (int)sidx[f];
    if (tid < 512) durf[b * 512 + tid] = (float)cnt[tid];
}

__global__ __launch_bounds__(128) void mas_fill(const int* __restrict__ idxg,
                                                float* __restrict__ masout)
{
    long row = blockIdx.x;
    int id = idxg[row];
    int tid = threadIdx.x;
    float4 v = make_float4(0.f, 0.f, 0.f, 0.f);
    if ((id >> 2) == tid) ((float*)&v)[id & 3] = 1.f;
    ((float4*)(masout + row * 512))[tid] = v;
}

// ------------------------- launcher -------------------------
extern "C" void kernel_launch(void* const* d_in, const int* in_sizes, int n_in,
                              void* d_out, int out_size) {
    const float* x   = (const float*)d_in[0];   // [32,512,512]
    const float* y   = (const float*)d_in[1];   // [32,2048,80]
    const float* pr  = (const float*)d_in[4];   // [32,512,2048]
    const float* kw1 = (const float*)d_in[5];
    const float* kb1 = (const float*)d_in[6];
    const float* kw2 = (const float*)d_in[7];   // [128][1024] = [N][K] already
    const float* kb2 = (const float*)d_in[8];
    const float* qw1 = (const float*)d_in[9];
    const float* qb1 = (const float*)d_in[10];
    const float* qw2 = (const float*)d_in[11];  // [80][160]
    const float* qb2 = (const float*)d_in[12];
    const float* qw3 = (const float*)d_in[13];  // [128][80]
    const float* qb3 = (const float*)d_in[14];

    float* out = (float*)d_out;
    float* out_logp = out;
    float* out_attn = out + 33554432L;
    float* out_mas  = out + 67108864L;
    float* out_dur  = out + 100663296L;

    float *Wt1, *Wq1, *h1, *kk, *k2, *hq1, *hq2, *qq, *q2, *logits, *plogT;
    unsigned* dirs; int* idxg;
    cudaGetSymbolAddress((void**)&Wt1, g_Wt1);
    cudaGetSymbolAddress((void**)&Wq1, g_Wq1);
    cudaGetSymbolAddress((void**)&h1, g_h1);
    cudaGetSymbolAddress((void**)&kk, g_kk);
    cudaGetSymbolAddress((void**)&k2, g_k2);
    cudaGetSymbolAddress((void**)&hq1, g_hq1);
    cudaGetSymbolAddress((void**)&hq2, g_hq2);
    cudaGetSymbolAddress((void**)&qq, g_qq);
    cudaGetSymbolAddress((void**)&q2, g_q2);
    cudaGetSymbolAddress((void**)&logits, g_logits);
    cudaGetSymbolAddress((void**)&plogT, g_plogT);
    cudaGetSymbolAddress((void**)&dirs, g_dirs);
    cudaGetSymbolAddress((void**)&idxg, g_idx);

    cudaFuncSetAttribute(mas_bwd, cudaFuncAttributeMaxDynamicSharedMemorySize, 131072);

    // weight prep (conv3 weights -> [N][K])
    wprep_convT<<<(1024 * 512 * 3 + 255) / 256, 256>>>(kw1, Wt1, 1024, 512);
    wprep_convT<<<(160 * 80 * 3 + 255) / 256, 256>>>(qw1, Wq1, 160, 80);

    // k path: conv3 (im2col) M=16384 N=1024 K=1536
    tgemm<1, false, 0><<<dim3(8, 128, 1), 256>>>(
        x, Wt1, kb1, h1, 1024, 1536, 0, 1536, 1024, 512, 512,
        0, 0, 0, nullptr, nullptr, 0, 0);
    // relu -> 1x1: M=16384 N=128 K=1024
    tgemm<0, true, 0><<<dim3(1, 128, 1), 256>>>(
        h1, kw2, kb2, kk, 128, 1024, 1024, 1024, 128, 0, 0,
        0, 0, 0, nullptr, nullptr, 0, 0);
    rowsq<<<16384 / 8, dim3(32, 8)>>>(kk, k2);

    // q path: conv3 M=65536 N=160 K=240
    tgemm<1, false, 0><<<dim3(2, 512, 1), 256>>>(
        y, Wq1, qb1, hq1, 160, 240, 0, 240, 160, 80, 2048,
        0, 0, 0, nullptr, nullptr, 0, 0);
    // relu -> 1x1: N=80 K=160
    tgemm<0, true, 0><<<dim3(1, 512, 1), 256>>>(
        hq1, qw2, qb2, hq2, 80, 160, 160, 160, 80, 0, 0,
        0, 0, 0, nullptr, nullptr, 0, 0);
    // relu -> 1x1: N=128 K=80
    tgemm<0, true, 0><<<dim3(1, 512, 1), 256>>>(
        hq2, qw3, qb3, qq, 128, 80, 80, 80, 128, 0, 0,
        0, 0, 0, nullptr, nullptr, 0, 0);
    rowsq<<<65536 / 8, dim3(32, 8)>>>(qq, q2);

    // prior transpose + log
    prior_t<<<dim3(16, 64, 32), dim3(32, 32)>>>(pr, plogT);

    // dist GEMM (batched): logits[b][t][s] = -TEMP*(q2+k2-2qk); B = kk rows directly
    tgemm<0, false, 1><<<dim3(4, 16, 32), 256>>>(
        qq, kk, nullptr, logits, 512, 128, 128, 128, 512, 0, 0,
        2048L * 128, 512L * 128, 2048L * 512, q2, k2, 2048, 512);

    // fused log_softmax + prior + softmax per row
    softmax_row<<<65536, 128>>>(logits, plogT, out_logp, out_attn);

    // MAS forward DP + backtrack + fill
    mas_fwd<<<32, 512>>>(out_attn, dirs);
    mas_bwd<<<32, 512, 131072>>>(dirs, idxg, out_dur);
    mas_fill<<<65536, 128>>>(idxg, out_mas);
}

// round 6
// speedup vs baseline: 2.0379x; 1.0888x over previous
#include <cuda_runtime.h>
#include <math.h>
#include <stdint.h>

#define T_EN 512
#define T_DE 2048
#define TEMPC 0.0005f
#define NEG_INF_DEV __int_as_float(0xff800000)

__device__ __forceinline__ uint32_t f2tf(float x) {
    uint32_t r;
    asm("cvt.rna.tf32.f32 %0, %1;" : "=r"(r) : "f"(x));
    return r;
}

// ------------------------- scratch (device globals) -------------------------
__device__ float g_Wt1[1024L * 1536];
__device__ float g_Wq1[160 * 240];
__device__ float g_h1[16384L * 1024];
__device__ float g_kk[16384L * 128];
__device__ float g_k2[16384];
__device__ float g_hq1[65536L * 160];
__device__ float g_hq2[65536L * 80];
__device__ float g_qq[65536L * 128];
__device__ float g_q2[65536];
__device__ float g_logits[33554432L];
__device__ unsigned g_dirs[32L * 2048 * 16];
__device__ int g_idx[32 * 2048];

// ------------------------- weight prep: [N][Cin][3] -> [N][dt*Cin+ci] -------------------------
__global__ void wprep_convT(const float* __restrict__ w, float* __restrict__ wt, int N, int Cin) {
    int idx = blockIdx.x * 256 + threadIdx.x;
    int total = N * Cin * 3;
    if (idx < total) {
        int n = idx / (Cin * 3);
        int rem = idx - n * (Cin * 3);
        int ci = rem / 3;
        int dt = rem - ci * 3;
        wt[(long)n * (3 * Cin) + dt * Cin + ci] = w[idx];
    }
}

// ------------------------- tf32 mma.sync GEMM v2 -------------------------
// C[M][N] = epi( act(A)[M][K] @ B^T ), B f32 [N][K] row-major.
// 128 threads, 4 warps (2m x 2n), warp tile 64x64, BK=16 double-buffered.
// Pair-packed smem: 16B unit = [ (rL,k), (rH,k), (rL,k+4), (rH,k+4) ] -> 1 LDS.128 per fragment.
// unit(ks,g,r8,kq) = ((ks*8+g)*8+r8)*4 + (kq ^ (r8&3))   [XOR swizzle]
// EPI0: +bias[n].  EPI1: -TEMP*(rown[m]+coln[n]-2*acc)
template <int IM2COL, int RELUIN, int EPI>
__global__ __launch_bounds__(128, 2) void tgemm(
    const float* __restrict__ A, const float* __restrict__ B,
    const float* __restrict__ bias, float* __restrict__ C,
    int N, int K, int ldA, int ldB, int ldC, int Cin, int Tlen,
    long sAb, long sBb, long sCb,
    const float* __restrict__ rown, const float* __restrict__ coln,
    int rstride, int cstride)
{
    __shared__ __align__(16) uint32_t smA[2][2048];
    __shared__ __align__(16) uint32_t smB[2][2048];
    const int tid = threadIdx.x, lane = tid & 31, wid = tid >> 5;
    const int bn = blockIdx.x * 128, bm = blockIdx.y * 128, bz = blockIdx.z;
    A += sAb * bz; B += sBb * bz;
    const int wm = wid >> 1, wn = wid & 1;

    float acc[4][8][4];
#pragma unroll
    for (int i = 0; i < 4; i++)
#pragma unroll
        for (int j = 0; j < 8; j++)
#pragma unroll
            for (int q = 0; q < 4; q++) acc[i][j][q] = 0.f;

    // ---- global loaders: f = tid + r*128 -> (row = f>>2, kq4 = (f&3)*4) ----
    auto ldA_g = [&](int kb, int r) -> float4 {
        int f = tid + r * 128;
        int row = f >> 2, kq4 = (f & 3) << 2;
        int gk = kb + kq4;
        float4 v = make_float4(0.f, 0.f, 0.f, 0.f);
        if (IM2COL) {
            int gm = bm + row;
            int bb = gm / Tlen;
            int t = gm - bb * Tlen;
            int dt = gk / Cin;
            int ci = gk - dt * Cin;
            int tt = t + dt - 1;
            if (tt >= 0 && tt < Tlen)
                v = *(const float4*)(A + ((long)(bb * Tlen + tt)) * Cin + ci);
        } else {
            v = *(const float4*)(A + (long)(bm + row) * ldA + gk);
            if (RELUIN) {
                v.x = fmaxf(v.x, 0.f); v.y = fmaxf(v.y, 0.f);
                v.z = fmaxf(v.z, 0.f); v.w = fmaxf(v.w, 0.f);
            }
        }
        return v;
    };
    auto ldB_g = [&](int kb, int r) -> float4 {
        int f = tid + r * 128;
        int col = f >> 2, kq4 = (f & 3) << 2;
        float4 v = make_float4(0.f, 0.f, 0.f, 0.f);
        if (bn + col < N)
            v = *(const float4*)(B + (long)(bn + col) * ldB + kb + kq4);
        return v;
    };
    // ---- pair-packed scatter store ----
    auto sts_tile = [&](uint32_t* smx, int r, float4 v) {
        int f = tid + r * 128;
        int row = f >> 2, l2 = f & 3;
        int ks = l2 >> 1, khalf = l2 & 1;
        int g = row >> 4, r8 = row & 7, rowhalf = (row >> 3) & 1;
        int base = ((ks * 8 + g) * 8 + r8) * 4;
        int slot = khalf * 2 + rowhalf;
        int sw = r8 & 3;
        smx[(base + (0 ^ sw)) * 4 + slot] = f2tf(v.x);
        smx[(base + (1 ^ sw)) * 4 + slot] = f2tf(v.y);
        smx[(base + (2 ^ sw)) * 4 + slot] = f2tf(v.z);
        smx[(base + (3 ^ sw)) * 4 + slot] = f2tf(v.w);
    };

    const int fr8 = lane >> 2;
    const int fsw = (lane & 3) ^ (fr8 & 3);

    float4 sa[4], sb[4];
    // ---- prologue ----
#pragma unroll
    for (int r = 0; r < 4; r++) {
        sa[r] = ldA_g(0, r);
        sb[r] = ldB_g(0, r);
    }
#pragma unroll
    for (int r = 0; r < 4; r++) {
        sts_tile(smA[0], r, sa[r]);
        sts_tile(smB[0], r, sb[r]);
    }
    __syncthreads();

    const int nc = K >> 4;
    for (int c = 0; c < nc; c++) {
        const int p = c & 1;
        if (c + 1 < nc) {
            int kb = (c + 1) << 4;
#pragma unroll
            for (int r = 0; r < 4; r++) {
                sa[r] = ldA_g(kb, r);
                sb[r] = ldB_g(kb, r);
            }
        }
#pragma unroll
        for (int ks = 0; ks < 2; ks++) {
            uint4 af[4];
#pragma unroll
            for (int mi = 0; mi < 4; mi++) {
                int g = wm * 4 + mi;
                af[mi] = *(const uint4*)&smA[p][(((ks * 8 + g) * 8 + fr8) * 4 + fsw) * 4];
            }
#pragma unroll
            for (int nb = 0; nb < 4; nb++) {
                int g = wn * 4 + nb;
                uint4 bf = *(const uint4*)&smB[p][(((ks * 8 + g) * 8 + fr8) * 4 + fsw) * 4];
#pragma unroll
                for (int mi = 0; mi < 4; mi++) {
                    asm volatile(
                        "mma.sync.aligned.m16n8k8.row.col.f32.tf32.tf32.f32 "
                        "{%0,%1,%2,%3}, {%4,%5,%6,%7}, {%8,%9}, {%0,%1,%2,%3};"
                        : "+f"(acc[mi][nb * 2][0]), "+f"(acc[mi][nb * 2][1]),
                          "+f"(acc[mi][nb * 2][2]), "+f"(acc[mi][nb * 2][3])
                        : "r"(af[mi].x), "r"(af[mi].y), "r"(af[mi].z), "r"(af[mi].w),
                          "r"(bf.x), "r"(bf.z));
                    asm volatile(
                        "mma.sync.aligned.m16n8k8.row.col.f32.tf32.tf32.f32 "
                        "{%0,%1,%2,%3}, {%4,%5,%6,%7}, {%8,%9}, {%0,%1,%2,%3};"
                        : "+f"(acc[mi][nb * 2 + 1][0]), "+f"(acc[mi][nb * 2 + 1][1]),
                          "+f"(acc[mi][nb * 2 + 1][2]), "+f"(acc[mi][nb * 2 + 1][3])
                        : "r"(af[mi].x), "r"(af[mi].y), "r"(af[mi].z), "r"(af[mi].w),
                          "r"(bf.y), "r"(bf.w));
                }
            }
        }
        if (c + 1 < nc) {
            int pn = p ^ 1;
#pragma unroll
            for (int r = 0; r < 4; r++) {
                sts_tile(smA[pn], r, sa[r]);
                sts_tile(smB[pn], r, sb[r]);
            }
        }
        __syncthreads();
    }

    // ---- epilogue ----
    C += sCb * bz;
#pragma unroll
    for (int mi = 0; mi < 4; mi++) {
        int r0 = bm + wm * 64 + mi * 16 + (lane >> 2);
        float ra0 = 0.f, ra1 = 0.f;
        if (EPI == 1) {
            ra0 = rown[(long)rstride * bz + r0];
            ra1 = rown[(long)rstride * bz + r0 + 8];
        }
#pragma unroll
        for (int ni = 0; ni < 8; ni++) {
            int colb = bn + wn * 64 + ni * 8;
            if (colb < N) {
                int col = colb + (lane & 3) * 2;
                float2 v0, v1;
                if (EPI == 0) {
                    float bb0 = bias[col], bb1 = bias[col + 1];
                    v0.x = acc[mi][ni][0] + bb0; v0.y = acc[mi][ni][1] + bb1;
                    v1.x = acc[mi][ni][2] + bb0; v1.y = acc[mi][ni][3] + bb1;
                } else {
                    float cn0 = coln[(long)cstride * bz + col];
                    float cn1 = coln[(long)cstride * bz + col + 1];
                    v0.x = -TEMPC * (ra0 + cn0 - 2.f * acc[mi][ni][0]);
                    v0.y = -TEMPC * (ra0 + cn1 - 2.f * acc[mi][ni][1]);
                    v1.x = -TEMPC * (ra1 + cn0 - 2.f * acc[mi][ni][2]);
                    v1.y = -TEMPC * (ra1 + cn1 - 2.f * acc[mi][ni][3]);
                }
                *(float2*)(C + (long)r0 * ldC + col) = v0;
                *(float2*)(C + (long)(r0 + 8) * ldC + col) = v1;
            }
        }
    }
}

// ------------------------- row squared-norms -------------------------
__global__ void rowsq(const float* __restrict__ X, float* __restrict__ out) {
    int row = blockIdx.x * 8 + threadIdx.y;
    const float4* p = (const float4*)(X + (long)row * 128);
    float4 a = p[threadIdx.x];
    float s = a.x * a.x + a.y * a.y + a.z * a.z + a.w * a.w;
#pragma unroll
    for (int o = 16; o; o >>= 1) s += __shfl_xor_sync(0xffffffffu, s, o);
    if (threadIdx.x == 0) out[row] = s;
}

// ------------------------- fused prior + log_softmax + softmax -------------------------
// block: 512 threads = 16 warps; handles (b, 16 t-rows); one warp per row.
// logp = v - lse + log(prior+1e-8); attn = e*(prior+1e-8)/sum(e*(prior+1e-8)), e = exp(v-m)
__global__ __launch_bounds__(512) void softprior(
    const float* __restrict__ logits, const float* __restrict__ prior,
    float* __restrict__ out_logp, float* __restrict__ out_attn)
{
    __shared__ float sp[512][17];
    const int b = blockIdx.y, t0 = blockIdx.x * 16;
    const int tid = threadIdx.x, lane = tid & 31, wid = tid >> 5;
    // stage prior[b][s][t0..t0+15] -> sp[s][tt]
#pragma unroll
    for (int i = 0; i < 4; i++) {
        int f = tid + i * 512;          // 0..2047 float4s
        int s = f >> 2;
        int tt4 = (f & 3) * 4;
        float4 v = *(const float4*)(prior + ((long)(b * 512 + s)) * 2048 + t0 + tt4);
        sp[s][tt4 + 0] = v.x; sp[s][tt4 + 1] = v.y;
        sp[s][tt4 + 2] = v.z; sp[s][tt4 + 3] = v.w;
    }
    __syncthreads();

    const long row = (long)b * 2048 + t0 + wid;
    const float* lrow = logits + row * 512;
    float v[16], e[16], p[16];
#pragma unroll
    for (int i = 0; i < 16; i++) v[i] = lrow[lane + 32 * i];
    float m = v[0];
#pragma unroll
    for (int i = 1; i < 16; i++) m = fmaxf(m, v[i]);
#pragma unroll
    for (int o = 16; o; o >>= 1) m = fmaxf(m, __shfl_xor_sync(0xffffffffu, m, o));
    float s1 = 0.f;
#pragma unroll
    for (int i = 0; i < 16; i++) { e[i] = __expf(v[i] - m); s1 += e[i]; }
#pragma unroll
    for (int o = 16; o; o >>= 1) s1 += __shfl_xor_sync(0xffffffffu, s1, o);
    float lse = m + __logf(s1);
    float den = 0.f;
#pragma unroll
    for (int i = 0; i < 16; i++) {
        p[i] = sp[lane + 32 * i][wid] + 1e-8f;
        den += e[i] * p[i];
    }
#pragma unroll
    for (int o = 16; o; o >>= 1) den += __shfl_xor_sync(0xffffffffu, den, o);
    float inv = 1.f / den;
    float* lpo = out_logp + row * 512;
    float* ao = out_attn + row * 512;
#pragma unroll
    for (int i = 0; i < 16; i++) {
        lpo[lane + 32 * i] = v[i] - lse + __logf(p[i]);
        ao[lane + 32 * i] = e[i] * p[i] * inv;
    }
}

// ------------------------- MAS forward DP -------------------------
__global__ __launch_bounds__(512) void mas_fwd(const float* __restrict__ attn,
                                               unsigned* __restrict__ dirs)
{
    const int b = blockIdx.x;
    const int i = threadIdx.x;
    __shared__ float vbuf[2][513];
    if (i == 0) { vbuf[0][0] = NEG_INF_DEV; vbuf[1][0] = NEG_INF_DEV; }
    float v = 0.f;
    vbuf[0][i + 1] = 0.f;
    __syncthreads();
    const float* arow = attn + (long)b * T_DE * T_EN + i;
    const unsigned lane = i & 31, wid = i >> 5;
    unsigned* drow = dirs + (long)b * T_DE * 16 + wid;
    float pf[8];
#pragma unroll
    for (int r = 0; r < 8; r++) pf[r] = arow[r * 512];
    int p = 0;
    for (int jj = 0; jj < 2048; jj += 8) {
#pragma unroll
        for (int r = 0; r < 8; r++) {
            int j = jj + r;
            float vj = pf[r];
            if (jj + 8 + r < 2048) pf[r] = arow[(jj + 8 + r) * 512];
            float vl = vbuf[p][i];
            bool dir = (v >= vl);
            unsigned bal = __ballot_sync(0xffffffffu, dir);
            if (lane == 0) drow[(long)j * 16] = bal;
            float vmax = dir ? v : vl;
            v = (i <= j) ? (vmax + vj) : NEG_INF_DEV;
            vbuf[p ^ 1][i + 1] = v;
            __syncthreads();
            p ^= 1;
        }
    }
}

// ------------------------- MAS backtrack -------------------------
__global__ __launch_bounds__(512) void mas_bwd(const unsigned* __restrict__ dirs,
                                               int* __restrict__ idxg,
                                               float* __restrict__ durf)
{
    extern __shared__ unsigned sd[];
    __shared__ unsigned short sidx[2048];
    __shared__ int cnt[512];
    int b = blockIdx.x, tid = threadIdx.x;
    for (int f = tid; f < 2048 * 16; f += 512) sd[f] = dirs[(long)b * 2048 * 16 + f];
    if (tid < 512) cnt[tid] = 0;
    __syncthreads();
    if (tid == 0) {
        int idx = T_EN - 1;
        for (int j = 2047; j >= 0; j--) {
            sidx[j] = (unsigned short)idx;
            cnt[idx]++;
            unsigned w = sd[j * 16 + (idx >> 5)];
            int d = (w >> (idx & 31)) & 1;
            idx += d - 1;
        }
    }
    __syncthreads();
    for (int f = tid; f < 2048; f += 512) idxg[b * 2048 + f] = (int)sidx[f];
    if (tid < 512) durf[b * 512 + tid] = (float)cnt[tid];
}

__global__ __launch_bounds__(128) void mas_fill(const int* __restrict__ idxg,
                                                float* __restrict__ masout)
{
    long row = blockIdx.x;
    int id = idxg[row];
    int tid = threadIdx.x;
    float4 v = make_float4(0.f, 0.f, 0.f, 0.f);
    if ((id >> 2) == tid) ((float*)&v)[id & 3] = 1.f;
    ((float4*)(masout + row * 512))[tid] = v;
}

// ------------------------- launcher -------------------------
extern "C" void kernel_launch(void* const* d_in, const int* in_sizes, int n_in,
                              void* d_out, int out_size) {
    const float* x   = (const float*)d_in[0];   // [32,512,512]
    const float* y   = (const float*)d_in[1];   // [32,2048,80]
    const float* pr  = (const float*)d_in[4];   // [32,512,2048]
    const float* kw1 = (const float*)d_in[5];
    const float* kb1 = (const float*)d_in[6];
    const float* kw2 = (const float*)d_in[7];   // [128][1024] = [N][K]
    const float* kb2 = (const float*)d_in[8];
    const float* qw1 = (const float*)d_in[9];
    const float* qb1 = (const float*)d_in[10];
    const float* qw2 = (const float*)d_in[11];  // [80][160]
    const float* qb2 = (const float*)d_in[12];
    const float* qw3 = (const float*)d_in[13];  // [128][80]
    const float* qb3 = (const float*)d_in[14];

    float* out = (float*)d_out;
    float* out_logp = out;
    float* out_attn = out + 33554432L;
    float* out_mas  = out + 67108864L;
    float* out_dur  = out + 100663296L;

    float *Wt1, *Wq1, *h1, *kk, *k2, *hq1, *hq2, *qq, *q2, *logits;
    unsigned* dirs; int* idxg;
    cudaGetSymbolAddress((void**)&Wt1, g_Wt1);
    cudaGetSymbolAddress((void**)&Wq1, g_Wq1);
    cudaGetSymbolAddress((void**)&h1, g_h1);
    cudaGetSymbolAddress((void**)&kk, g_kk);
    cudaGetSymbolAddress((void**)&k2, g_k2);
    cudaGetSymbolAddress((void**)&hq1, g_hq1);
    cudaGetSymbolAddress((void**)&hq2, g_hq2);
    cudaGetSymbolAddress((void**)&qq, g_qq);
    cudaGetSymbolAddress((void**)&q2, g_q2);
    cudaGetSymbolAddress((void**)&logits, g_logits);
    cudaGetSymbolAddress((void**)&dirs, g_dirs);
    cudaGetSymbolAddress((void**)&idxg, g_idx);

    cudaFuncSetAttribute(mas_bwd, cudaFuncAttributeMaxDynamicSharedMemorySize, 131072);

    // weight prep (conv3 weights -> [N][K])
    wprep_convT<<<(1024 * 512 * 3 + 255) / 256, 256>>>(kw1, Wt1, 1024, 512);
    wprep_convT<<<(160 * 80 * 3 + 255) / 256, 256>>>(qw1, Wq1, 160, 80);

    // k path: conv3 (im2col) M=16384 N=1024 K=1536
    tgemm<1, 0, 0><<<dim3(8, 128, 1), 128>>>(
        x, Wt1, kb1, h1, 1024, 1536, 0, 1536, 1024, 512, 512,
        0, 0, 0, nullptr, nullptr, 0, 0);
    // relu -> 1x1: M=16384 N=128 K=1024
    tgemm<0, 1, 0><<<dim3(1, 128, 1), 128>>>(
        h1, kw2, kb2, kk, 128, 1024, 1024, 1024, 128, 0, 0,
        0, 0, 0, nullptr, nullptr, 0, 0);
    rowsq<<<16384 / 8, dim3(32, 8)>>>(kk, k2);

    // q path: conv3 M=65536 N=160 K=240
    tgemm<1, 0, 0><<<dim3(2, 512, 1), 128>>>(
        y, Wq1, qb1, hq1, 160, 240, 0, 240, 160, 80, 2048,
        0, 0, 0, nullptr, nullptr, 0, 0);
    // relu -> 1x1: N=80 K=160
    tgemm<0, 1, 0><<<dim3(1, 512, 1), 128>>>(
        hq1, qw2, qb2, hq2, 80, 160, 160, 160, 80, 0, 0,
        0, 0, 0, nullptr, nullptr, 0, 0);
    // relu -> 1x1: N=128 K=80
    tgemm<0, 1, 0><<<dim3(1, 512, 1), 128>>>(
        hq2, qw3, qb3, qq, 128, 80, 80, 80, 128, 0, 0,
        0, 0, 0, nullptr, nullptr, 0, 0);
    rowsq<<<65536 / 8, dim3(32, 8)>>>(qq, q2);

    // dist GEMM (batched): logits[b][t][s] = -TEMP*(q2+k2-2qk); B = kk rows directly
    tgemm<0, 0, 1><<<dim3(4, 16, 32), 128>>>(
        qq, kk, nullptr, logits, 512, 128, 128, 128, 512, 0, 0,
        2048L * 128, 512L * 128, 2048L * 512, q2, k2, 2048, 512);

    // fused prior + log_softmax + softmax
    softprior<<<dim3(128, 32), 512>>>(logits, pr, out_logp, out_attn);

    // MAS forward DP + backtrack + fill
    mas_fwd<<<32, 512>>>(out_attn, dirs);
    mas_bwd<<<32, 512, 131072>>>(dirs, idxg, out_dur);
    mas_fill<<<65536, 128>>>(idxg, out_mas);
}

// round 7
// speedup vs baseline: 2.3443x; 1.1503x over previous
#include <cuda_runtime.h>
#include <math.h>
#include <stdint.h>

#define T_EN 512
#define T_DE 2048
#define TEMPC 0.0005f
#define NEG_INF_DEV __int_as_float(0xff800000)

__device__ __forceinline__ uint32_t f2tf(float x) {
    uint32_t r;
    asm("cvt.rna.tf32.f32 %0, %1;" : "=r"(r) : "f"(x));
    return r;
}
__device__ __forceinline__ float rtf(float x) { return __uint_as_float(f2tf(x)); }
__device__ __forceinline__ uint32_t smem_u32(const void* p) {
    uint32_t a;
    asm("{ .reg .u64 t; cvta.to.shared.u64 t, %1; cvt.u32.u64 %0, t; }" : "=r"(a) : "l"(p));
    return a;
}

// ------------------------- scratch (device globals) -------------------------
__device__ float g_xr[32L * 512 * 512];
__device__ float g_yr[32L * 2048 * 80];
__device__ float g_Wt1[1024L * 1536];
__device__ float g_Wq1[160 * 240];
__device__ float g_Wk2[128 * 1024];
__device__ float g_Wq2[80 * 160];
__device__ float g_Wq3[128 * 80];
__device__ float g_h1[16384L * 1024];
__device__ float g_kk[16384L * 128];
__device__ float g_k2[16384];
__device__ float g_hq1[65536L * 160];
__device__ float g_hq2[65536L * 80];
__device__ float g_qq[65536L * 128];
__device__ float g_q2[65536];
__device__ float g_logits[33554432L];
__device__ unsigned g_dirs[32L * 2048 * 16];
__device__ int g_idx[32 * 2048];

// ------------------------- prep kernels -------------------------
// conv weight [N][Cin][3] -> tf32-rounded [N][dt*Cin+ci]
__global__ void wprep_convT(const float* __restrict__ w, float* __restrict__ wt, int N, int Cin) {
    int idx = blockIdx.x * 256 + threadIdx.x;
    int total = N * Cin * 3;
    if (idx < total) {
        int n = idx / (Cin * 3);
        int rem = idx - n * (Cin * 3);
        int ci = rem / 3;
        int dt = rem - ci * 3;
        wt[(long)n * (3 * Cin) + dt * Cin + ci] = rtf(w[idx]);
    }
}
// tf32-rounded copy (vectorized)
__global__ void roundcopy4(const float* __restrict__ in, float* __restrict__ out, int n4) {
    int i = blockIdx.x * 256 + threadIdx.x;
    if (i < n4) {
        float4 v = ((const float4*)in)[i];
        v.x = rtf(v.x); v.y = rtf(v.y); v.z = rtf(v.z); v.w = rtf(v.w);
        ((float4*)out)[i] = v;
    }
}

// ------------------------- tf32 cp.async pipelined GEMM -------------------------
// C = epi( A[M][K] @ B^T ), B tf32-rounded f32 [N][K] row-major, A tf32-rounded.
// 256 threads, 8 warps (4m x 2n), warp tile 32x64, BK=32, 3-stage cp.async pipeline.
// smem per tile: [row][32] floats, 16B-unit swizzle: unit kq -> kq ^ (row&7).
// IM2COL: A gathered from X[b][t][Cin], conv k=3 pad=1, k = dt*Cin+ci.
// EPI0: round(acc+bias). EPI1: round(relu(acc+bias)). EPI2: -TEMP*(rown+coln-2*acc)
template <int IM2COL, int EPI>
__global__ __launch_bounds__(256, 2) void tgemm(
    const float* __restrict__ A, const float* __restrict__ B,
    const float* __restrict__ bias, float* __restrict__ C,
    int N, int Kreal, int ldA, int ldB, int ldC, int Cin, int Tlen,
    long sAb, long sBb, long sCb,
    const float* __restrict__ rown, const float* __restrict__ coln,
    int rstride, int cstride)
{
    extern __shared__ float smf[];           // 3 stages x (A 4096 + B 4096) floats
    const uint32_t smb = smem_u32(smf);
    const int tid = threadIdx.x, lane = tid & 31, wid = tid >> 5;
    const int bn = blockIdx.x * 128, bm = blockIdx.y * 128, bz = blockIdx.z;
    A += sAb * bz; B += sBb * bz;
    const int wm = wid & 3, wn = wid >> 2;

    float acc[2][8][4];
#pragma unroll
    for (int i = 0; i < 2; i++)
#pragma unroll
        for (int j = 0; j < 8; j++)
#pragma unroll
            for (int q = 0; q < 4; q++) acc[i][j][q] = 0.f;

    const int nc = (Kreal + 31) >> 5;

    auto prefetch = [&](int c, int s) {
        const int kb = c << 5;
        const uint32_t sbase = smb + s * 32768u;
#pragma unroll
        for (int r = 0; r < 4; r++) {
            int f = tid + r * 256;               // 0..1023
            int row = f >> 3, kq = f & 7;
            int gk = kb + kq * 4;
            uint32_t dsw = (uint32_t)(row * 128 + ((kq ^ (row & 7)) << 4));
            // ---- A ----
            {
                const float* src = A;
                int sz = 0;
                if (gk < Kreal) {
                    if (IM2COL) {
                        int gm = bm + row;
                        int bb = gm / Tlen;
                        int t = gm - bb * Tlen;
                        int dt = gk / Cin;
                        int ci = gk - dt * Cin;
                        int tt = t + dt - 1;
                        if (tt >= 0 && tt < Tlen) {
                            src = A + ((long)(bb * Tlen + tt)) * Cin + ci;
                            sz = 16;
                        }
                    } else {
                        src = A + (long)(bm + row) * ldA + gk;
                        sz = 16;
                    }
                }
                asm volatile("cp.async.cg.shared.global [%0], [%1], 16, %2;"
                             :: "r"(sbase + dsw), "l"(src), "r"(sz) : "memory");
            }
            // ---- B ----
            {
                const float* src = B;
                int sz = 0;
                if ((bn + row) < N && gk < Kreal) {
                    src = B + (long)(bn + row) * ldB + gk;
                    sz = 16;
                }
                asm volatile("cp.async.cg.shared.global [%0], [%1], 16, %2;"
                             :: "r"(sbase + 16384u + dsw), "l"(src), "r"(sz) : "memory");
            }
        }
        asm volatile("cp.async.commit_group;" ::: "memory");
    };

    // prologue (nc >= 3 for all call sites)
    prefetch(0, 0);
    prefetch(1, 1);

    const int arow = wm * 32 + (lane >> 2);
    const int klo = lane & 3;

    for (int c = 0; c < nc; c++) {
        asm volatile("cp.async.wait_group 1;" ::: "memory");
        __syncthreads();
        if (c + 2 < nc) prefetch(c + 2, (c + 2) % 3);
        else asm volatile("cp.async.commit_group;" ::: "memory");

        const float* As = smf + (c % 3) * 8192;
        const float* Bs = As + 4096;
        auto ld = [&](const float* base, int row, int q) -> uint32_t {
            return __float_as_uint(base[row * 32 + ((q ^ (row & 7)) << 2) + klo]);
        };
#pragma unroll
        for (int ks = 0; ks < 4; ks++) {
            const int q0 = ks * 2, q1 = q0 + 1;
            uint32_t a[2][4];
#pragma unroll
            for (int mi = 0; mi < 2; mi++) {
                int r = arow + mi * 16;
                a[mi][0] = ld(As, r, q0);
                a[mi][1] = ld(As, r + 8, q0);
                a[mi][2] = ld(As, r, q1);
                a[mi][3] = ld(As, r + 8, q1);
            }
#pragma unroll
            for (int ni = 0; ni < 8; ni++) {
                int cb = wn * 64 + ni * 8 + (lane >> 2);
                uint32_t b0 = ld(Bs, cb, q0);
                uint32_t b1 = ld(Bs, cb, q1);
#pragma unroll
                for (int mi = 0; mi < 2; mi++) {
                    asm volatile(
                        "mma.sync.aligned.m16n8k8.row.col.f32.tf32.tf32.f32 "
                        "{%0,%1,%2,%3}, {%4,%5,%6,%7}, {%8,%9}, {%0,%1,%2,%3};"
                        : "+f"(acc[mi][ni][0]), "+f"(acc[mi][ni][1]),
                          "+f"(acc[mi][ni][2]), "+f"(acc[mi][ni][3])
                        : "r"(a[mi][0]), "r"(a[mi][1]), "r"(a[mi][2]), "r"(a[mi][3]),
                          "r"(b0), "r"(b1));
                }
            }
        }
        __syncthreads();
    }

    // ---- epilogue ----
    C += sCb * bz;
#pragma unroll
    for (int mi = 0; mi < 2; mi++) {
        int r0 = bm + wm * 32 + mi * 16 + (lane >> 2);
        float ra0 = 0.f, ra1 = 0.f;
        if (EPI == 2) {
            ra0 = rown[(long)rstride * bz + r0];
            ra1 = rown[(long)rstride * bz + r0 + 8];
        }
#pragma unroll
        for (int ni = 0; ni < 8; ni++) {
            int colb = bn + wn * 64 + ni * 8;
            if (colb < N) {
                int col = colb + (lane & 3) * 2;
                float2 v0, v1;
                if (EPI == 2) {
                    float cn0 = coln[(long)cstride * bz + col];
                    float cn1 = coln[(long)cstride * bz + col + 1];
                    v0.x = -TEMPC * (ra0 + cn0 - 2.f * acc[mi][ni][0]);
                    v0.y = -TEMPC * (ra0 + cn1 - 2.f * acc[mi][ni][1]);
                    v1.x = -TEMPC * (ra1 + cn0 - 2.f * acc[mi][ni][2]);
                    v1.y = -TEMPC * (ra1 + cn1 - 2.f * acc[mi][ni][3]);
                } else {
                    float bb0 = bias[col], bb1 = bias[col + 1];
                    v0.x = acc[mi][ni][0] + bb0; v0.y = acc[mi][ni][1] + bb1;
                    v1.x = acc[mi][ni][2] + bb0; v1.y = acc[mi][ni][3] + bb1;
                    if (EPI == 1) {
                        v0.x = fmaxf(v0.x, 0.f); v0.y = fmaxf(v0.y, 0.f);
                        v1.x = fmaxf(v1.x, 0.f); v1.y = fmaxf(v1.y, 0.f);
                    }
                    v0.x = rtf(v0.x); v0.y = rtf(v0.y);
                    v1.x = rtf(v1.x); v1.y = rtf(v1.y);
                }
                *(float2*)(C + (long)r0 * ldC + col) = v0;
                *(float2*)(C + (long)(r0 + 8) * ldC + col) = v1;
            }
        }
    }
}

// ------------------------- row squared-norms -------------------------
__global__ void rowsq(const float* __restrict__ X, float* __restrict__ out) {
    int row = blockIdx.x * 8 + threadIdx.y;
    const float4* p = (const float4*)(X + (long)row * 128);
    float4 a = p[threadIdx.x];
    float s = a.x * a.x + a.y * a.y + a.z * a.z + a.w * a.w;
#pragma unroll
    for (int o = 16; o; o >>= 1) s += __shfl_xor_sync(0xffffffffu, s, o);
    if (threadIdx.x == 0) out[row] = s;
}

// ------------------------- fused prior + log_softmax + softmax -------------------------
__global__ __launch_bounds__(512) void softprior(
    const float* __restrict__ logits, const float* __restrict__ prior,
    float* __restrict__ out_logp, float* __restrict__ out_attn)
{
    __shared__ float sp[512][17];
    const int b = blockIdx.y, t0 = blockIdx.x * 16;
    const int tid = threadIdx.x, lane = tid & 31, wid = tid >> 5;
#pragma unroll
    for (int i = 0; i < 4; i++) {
        int f = tid + i * 512;
        int s = f >> 2;
        int tt4 = (f & 3) * 4;
        float4 v = *(const float4*)(prior + ((long)(b * 512 + s)) * 2048 + t0 + tt4);
        sp[s][tt4 + 0] = v.x; sp[s][tt4 + 1] = v.y;
        sp[s][tt4 + 2] = v.z; sp[s][tt4 + 3] = v.w;
    }
    __syncthreads();

    const long row = (long)b * 2048 + t0 + wid;
    const float* lrow = logits + row * 512;
    float v[16], e[16], p[16];
#pragma unroll
    for (int i = 0; i < 16; i++) v[i] = lrow[lane + 32 * i];
    float m = v[0];
#pragma unroll
    for (int i = 1; i < 16; i++) m = fmaxf(m, v[i]);
#pragma unroll
    for (int o = 16; o; o >>= 1) m = fmaxf(m, __shfl_xor_sync(0xffffffffu, m, o));
    float s1 = 0.f;
#pragma unroll
    for (int i = 0; i < 16; i++) { e[i] = __expf(v[i] - m); s1 += e[i]; }
#pragma unroll
    for (int o = 16; o; o >>= 1) s1 += __shfl_xor_sync(0xffffffffu, s1, o);
    float lse = m + __logf(s1);
    float den = 0.f;
#pragma unroll
    for (int i = 0; i < 16; i++) {
        p[i] = sp[lane + 32 * i][wid] + 1e-8f;
        den += e[i] * p[i];
    }
#pragma unroll
    for (int o = 16; o; o >>= 1) den += __shfl_xor_sync(0xffffffffu, den, o);
    float inv = 1.f / den;
    float* lpo = out_logp + row * 512;
    float* ao = out_attn + row * 512;
#pragma unroll
    for (int i = 0; i < 16; i++) {
        lpo[lane + 32 * i] = v[i] - lse + __logf(p[i]);
        ao[lane + 32 * i] = e[i] * p[i] * inv;
    }
}

// ------------------------- MAS forward DP -------------------------
__global__ __launch_bounds__(512) void mas_fwd(const float* __restrict__ attn,
                                               unsigned* __restrict__ dirs)
{
    const int b = blockIdx.x;
    const int i = threadIdx.x;
    __shared__ float vbuf[2][513];
    if (i == 0) { vbuf[0][0] = NEG_INF_DEV; vbuf[1][0] = NEG_INF_DEV; }
    float v = 0.f;
    vbuf[0][i + 1] = 0.f;
    __syncthreads();
    const float* arow = attn + (long)b * T_DE * T_EN + i;
    const unsigned lane = i & 31, wid = i >> 5;
    unsigned* drow = dirs + (long)b * T_DE * 16 + wid;
    float pf[8];
#pragma unroll
    for (int r = 0; r < 8; r++) pf[r] = arow[r * 512];
    int p = 0;
    for (int jj = 0; jj < 2048; jj += 8) {
#pragma unroll
        for (int r = 0; r < 8; r++) {
            int j = jj + r;
            float vj = pf[r];
            if (jj + 8 + r < 2048) pf[r] = arow[(jj + 8 + r) * 512];
            float vl = vbuf[p][i];
            bool dir = (v >= vl);
            unsigned bal = __ballot_sync(0xffffffffu, dir);
            if (lane == 0) drow[(long)j * 16] = bal;
            float vmax = dir ? v : vl;
            v = (i <= j) ? (vmax + vj) : NEG_INF_DEV;
            vbuf[p ^ 1][i + 1] = v;
            __syncthreads();
            p ^= 1;
        }
    }
}

// ------------------------- MAS backtrack -------------------------
__global__ __launch_bounds__(512) void mas_bwd(const unsigned* __restrict__ dirs,
                                               int* __restrict__ idxg,
                                               float* __restrict__ durf)
{
    extern __shared__ unsigned sd[];
    __shared__ unsigned short sidx[2048];
    __shared__ int cnt[512];
    int b = blockIdx.x, tid = threadIdx.x;
    for (int f = tid; f < 2048 * 16; f += 512) sd[f] = dirs[(long)b * 2048 * 16 + f];
    if (tid < 512) cnt[tid] = 0;
    __syncthreads();
    if (tid == 0) {
        int idx = T_EN - 1;
        for (int j = 2047; j >= 0; j--) {
            sidx[j] = (unsigned short)idx;
            cnt[idx]++;
            unsigned w = sd[j * 16 + (idx >> 5)];
            int d = (w >> (idx & 31)) & 1;
            idx += d - 1;
        }
    }
    __syncthreads();
    for (int f = tid; f < 2048; f += 512) idxg[b * 2048 + f] = (int)sidx[f];
    if (tid < 512) durf[b * 512 + tid] = (float)cnt[tid];
}

__global__ __launch_bounds__(128) void mas_fill(const int* __restrict__ idxg,
                                                float* __restrict__ masout)
{
    long row = blockIdx.x;
    int id = idxg[row];
    int tid = threadIdx.x;
    float4 v = make_float4(0.f, 0.f, 0.f, 0.f);
    if ((id >> 2) == tid) ((float*)&v)[id & 3] = 1.f;
    ((float4*)(masout + row * 512))[tid] = v;
}

// ------------------------- launcher -------------------------
#define GSMEM 98304

extern "C" void kernel_launch(void* const* d_in, const int* in_sizes, int n_in,
                              void* d_out, int out_size) {
    const float* x   = (const float*)d_in[0];   // [32,512,512]
    const float* y   = (const float*)d_in[1];   // [32,2048,80]
    const float* pr  = (const float*)d_in[4];   // [32,512,2048]
    const float* kw1 = (const float*)d_in[5];
    const float* kb1 = (const float*)d_in[6];
    const float* kw2 = (const float*)d_in[7];   // [128][1024]
    const float* kb2 = (const float*)d_in[8];
    const float* qw1 = (const float*)d_in[9];
    const float* qb1 = (const float*)d_in[10];
    const float* qw2 = (const float*)d_in[11];  // [80][160]
    const float* qb2 = (const float*)d_in[12];
    const float* qw3 = (const float*)d_in[13];  // [128][80]
    const float* qb3 = (const float*)d_in[14];

    float* out = (float*)d_out;
    float* out_logp = out;
    float* out_attn = out + 33554432L;
    float* out_mas  = out + 67108864L;
    float* out_dur  = out + 100663296L;

    float *xr, *yr, *Wt1, *Wq1, *Wk2, *Wq2, *Wq3;
    float *h1, *kk, *k2, *hq1, *hq2, *qq, *q2, *logits;
    unsigned* dirs; int* idxg;
    cudaGetSymbolAddress((void**)&xr, g_xr);
    cudaGetSymbolAddress((void**)&yr, g_yr);
    cudaGetSymbolAddress((void**)&Wt1, g_Wt1);
    cudaGetSymbolAddress((void**)&Wq1, g_Wq1);
    cudaGetSymbolAddress((void**)&Wk2, g_Wk2);
    cudaGetSymbolAddress((void**)&Wq2, g_Wq2);
    cudaGetSymbolAddress((void**)&Wq3, g_Wq3);
    cudaGetSymbolAddress((void**)&h1, g_h1);
    cudaGetSymbolAddress((void**)&kk, g_kk);
    cudaGetSymbolAddress((void**)&k2, g_k2);
    cudaGetSymbolAddress((void**)&hq1, g_hq1);
    cudaGetSymbolAddress((void**)&hq2, g_hq2);
    cudaGetSymbolAddress((void**)&qq, g_qq);
    cudaGetSymbolAddress((void**)&q2, g_q2);
    cudaGetSymbolAddress((void**)&logits, g_logits);
    cudaGetSymbolAddress((void**)&dirs, g_dirs);
    cudaGetSymbolAddress((void**)&idxg, g_idx);

    cudaFuncSetAttribute(tgemm<1, 1>, cudaFuncAttributeMaxDynamicSharedMemorySize, GSMEM);
    cudaFuncSetAttribute(tgemm<0, 0>, cudaFuncAttributeMaxDynamicSharedMemorySize, GSMEM);
    cudaFuncSetAttribute(tgemm<0, 1>, cudaFuncAttributeMaxDynamicSharedMemorySize, GSMEM);
    cudaFuncSetAttribute(tgemm<0, 2>, cudaFuncAttributeMaxDynamicSharedMemorySize, GSMEM);
    cudaFuncSetAttribute(mas_bwd, cudaFuncAttributeMaxDynamicSharedMemorySize, 131072);

    // prep: tf32-round everything entering MMAs
    roundcopy4<<<(8388608 / 4 + 255) / 256, 256>>>(x, xr, 8388608 / 4);
    roundcopy4<<<(5242880 / 4 + 255) / 256, 256>>>(y, yr, 5242880 / 4);
    wprep_convT<<<(1024 * 512 * 3 + 255) / 256, 256>>>(kw1, Wt1, 1024, 512);
    wprep_convT<<<(160 * 80 * 3 + 255) / 256, 256>>>(qw1, Wq1, 160, 80);
    roundcopy4<<<(131072 / 4 + 255) / 256, 256>>>(kw2, Wk2, 131072 / 4);
    roundcopy4<<<(12800 / 4 + 255) / 256, 256>>>(qw2, Wq2, 12800 / 4);
    roundcopy4<<<(10240 / 4 + 255) / 256, 256>>>(qw3, Wq3, 10240 / 4);

    // k path: conv3 (im2col) M=16384 N=1024 K=1536, output relu'd
    tgemm<1, 1><<<dim3(8, 128, 1), 256, GSMEM>>>(
        xr, Wt1, kb1, h1, 1024, 1536, 0, 1536, 1024, 512, 512,
        0, 0, 0, nullptr, nullptr, 0, 0);
    // 1x1: M=16384 N=128 K=1024 -> kk (no relu)
    tgemm<0, 0><<<dim3(1, 128, 1), 256, GSMEM>>>(
        h1, Wk2, kb2, kk, 128, 1024, 1024, 1024, 128, 0, 0,
        0, 0, 0, nullptr, nullptr, 0, 0);
    rowsq<<<16384 / 8, dim3(32, 8)>>>(kk, k2);

    // q path: conv3 M=65536 N=160 K=240, relu'd
    tgemm<1, 1><<<dim3(2, 512, 1), 256, GSMEM>>>(
        yr, Wq1, qb1, hq1, 160, 240, 0, 240, 160, 80, 2048,
        0, 0, 0, nullptr, nullptr, 0, 0);
    // 1x1: N=80 K=160, relu'd
    tgemm<0, 1><<<dim3(1, 512, 1), 256, GSMEM>>>(
        hq1, Wq2, qb2, hq2, 80, 160, 160, 160, 80, 0, 0,
        0, 0, 0, nullptr, nullptr, 0, 0);
    // 1x1: N=128 K=80 -> qq (no relu)
    tgemm<0, 0><<<dim3(1, 512, 1), 256, GSMEM>>>(
        hq2, Wq3, qb3, qq, 128, 80, 80, 80, 128, 0, 0,
        0, 0, 0, nullptr, nullptr, 0, 0);
    rowsq<<<65536 / 8, dim3(32, 8)>>>(qq, q2);

    // dist GEMM (batched): logits[b][t][s] = -TEMP*(q2+k2-2qk)
    tgemm<0, 2><<<dim3(4, 16, 32), 256, GSMEM>>>(
        qq, kk, nullptr, logits, 512, 128, 128, 128, 512, 0, 0,
        2048L * 128, 512L * 128, 2048L * 512, q2, k2, 2048, 512);

    // fused prior + log_softmax + softmax
    softprior<<<dim3(128, 32), 512>>>(logits, pr, out_logp, out_attn);

    // MAS forward DP + backtrack + fill
    mas_fwd<<<32, 512>>>(out_attn, dirs);
    mas_bwd<<<32, 512, 131072>>>(dirs, idxg, out_dur);
    mas_fill<<<65536, 128>>>(idxg, out_mas);
}